// round 1
// baseline (speedup 1.0000x reference)
#include <cuda_runtime.h>
#include <cuda_bf16.h>

// out[b,s,e] = W_e[e, tokens[b,s]] + W_p[s,e]
// tokens: (2,2048) int32, W_e: (1024,32000) f32, W_p: (2048,1024) f32
// out: (2,2048,1024) f32

#define B 2
#define S 2048
#define E 1024
#define V 32000

__global__ void embedding_gather_kernel(const int* __restrict__ tokens,
                                        const float* __restrict__ W_e,
                                        const float* __restrict__ W_p,
                                        float* __restrict__ out) {
    // One thread per float4 of output. Total float4s = B*S*E/4 = 1,048,576.
    int idx = blockIdx.x * blockDim.x + threadIdx.x;
    int e4 = idx & (E / 4 - 1);      // 0..255  (float4 index along E)
    int bs = idx >> 8;               // 0..4095 (b*S + s)
    int s  = bs & (S - 1);

    int v = __ldg(&tokens[bs]);      // warp-uniform: 256 threads share one (b,s)

    // Column gather: 4 independent scalar loads, stride V floats (uncoalescable
    // by construction of W_e's layout; sectors dedup in L2 across tokens).
    const float* col = W_e + (size_t)(e4 * 4) * V + v;
    float a0 = __ldg(col);
    float a1 = __ldg(col + V);
    float a2 = __ldg(col + 2 * V);
    float a3 = __ldg(col + 3 * V);

    // Positional add: coalesced float4, reused across the two batches via L2.
    float4 p = *reinterpret_cast<const float4*>(W_p + (size_t)s * E + e4 * 4);

    float4 r;
    r.x = a0 + p.x;
    r.y = a1 + p.y;
    r.z = a2 + p.z;
    r.w = a3 + p.w;
    reinterpret_cast<float4*>(out)[idx] = r;
}

extern "C" void kernel_launch(void* const* d_in, const int* in_sizes, int n_in,
                              void* d_out, int out_size) {
    const int*   tokens = (const int*)d_in[0];
    const float* W_e    = (const float*)d_in[1];
    const float* W_p    = (const float*)d_in[2];
    float*       out    = (float*)d_out;

    const int total4 = B * S * E / 4;      // 1,048,576
    const int tpb = 256;
    embedding_gather_kernel<<<total4 / tpb, tpb>>>(tokens, W_e, W_p, out);
}

// round 2
// speedup vs baseline: 1.3529x; 1.3529x over previous
#include <cuda_runtime.h>
#include <cuda_bf16.h>

// out[b,s,e] = W_e[e, tokens[b,s]] + W_p[s,e]
// tokens: (2,2048) int32, W_e: (1024,32000) f32, W_p: (2048,1024) f32
// out: (2,2048,1024) f32
//
// Grid is e-chunk-major / token-fast: chunk of 256 e-rows, all 4096 tokens
// swept inside one chunk before moving on. This bounds the L2 working set of
// the W_e gather to ~28MB per chunk so duplicate v-granules dedup in L2
// instead of re-fetching from DRAM.

#define B 2
#define S 2048
#define E 1024
#define V 32000

#define NCHUNK 4        // e-chunks of 256 rows each
#define TOK_PER_BLK 4   // tokens per block (256 threads = 4 tok x 64 float4)

__global__ void embedding_gather_kernel(const int* __restrict__ tokens,
                                        const float* __restrict__ W_e,
                                        const float* __restrict__ W_p,
                                        float* __restrict__ out) {
    // blockIdx.x in [0, 4096): token-group fast, e-chunk slow.
    int group = blockIdx.x & 1023;        // 1024 token groups
    int chunk = blockIdx.x >> 10;         // 0..3

    int t       = threadIdx.x;
    int tok_sub = t >> 6;                 // 0..3  (warp-uniform)
    int eq      = t & 63;                 // 0..63 (float4 slot within chunk)

    int tok = group * TOK_PER_BLK + tok_sub;   // bs in [0, 4096)
    int s   = tok & (S - 1);
    int e4  = chunk * 64 + eq;                 // float4 index in [0, 256)
    int e0  = e4 * 4;

    int v = __ldg(&tokens[tok]);          // warp-uniform broadcast

    // Column gather: 4 independent scalar loads at stride V (layout-forced).
    const float* col = W_e + (size_t)e0 * V + v;
    float a0 = __ldg(col);
    float a1 = __ldg(col + V);
    float a2 = __ldg(col + 2 * V);
    float a3 = __ldg(col + 3 * V);

    // Positional add: coalesced float4.
    float4 p = *reinterpret_cast<const float4*>(W_p + (size_t)s * E + e0);

    float4 r;
    r.x = a0 + p.x;
    r.y = a1 + p.y;
    r.z = a2 + p.z;
    r.w = a3 + p.w;

    // Streaming store: don't let the 16MB output evict the gather working set.
    __stcs(reinterpret_cast<float4*>(out + (size_t)tok * E + e0), r);
}

extern "C" void kernel_launch(void* const* d_in, const int* in_sizes, int n_in,
                              void* d_out, int out_size) {
    const int*   tokens = (const int*)d_in[0];
    const float* W_e    = (const float*)d_in[1];
    const float* W_p    = (const float*)d_in[2];
    float*       out    = (float*)d_out;

    // 4096 blocks x 256 threads = 1M threads, one float4 each.
    embedding_gather_kernel<<<NCHUNK * 1024, 256>>>(tokens, W_e, W_p, out);
}